// round 14
// baseline (speedup 1.0000x reference)
#include <cuda_runtime.h>
#include <cuda_fp16.h>
#include <math.h>
#include <stdint.h>

#define N_TOK 4096
#define H_DIM 1024
#define F_DIM 4096
#define NE 8
#define CAP 1280   // min(max(4, ceil(2*1.25*4096/8)), 4096)

// ---------------- scratch (device globals; no allocations allowed) ----------------
__device__ __half g_w1f [(size_t)NE * H_DIM * F_DIM];
__device__ __half g_w2f [(size_t)NE * F_DIM * H_DIM];
__device__ __half g_sw1f[(size_t)H_DIM * F_DIM];
__device__ __half g_sw2f[(size_t)F_DIM * H_DIM];
__device__ __half g_xf [(size_t)N_TOK * H_DIM];
__device__ __half g_eif[(size_t)NE * CAP * H_DIM];
__device__ __half g_hmf[(size_t)NE * CAP * F_DIM];
__device__ __half g_smf[(size_t)N_TOK * F_DIM];
__device__ float g_expert_out[(size_t)NE * CAP * H_DIM];
__device__ int   g_e1[N_TOK];
__device__ int   g_e2[N_TOK];
__device__ int   g_slot1[N_TOK];
__device__ int   g_slot2[N_TOK];
__device__ float g_g1[N_TOK];
__device__ float g_g2[N_TOK];
__device__ int   g_cnt1[NE];
__device__ int   g_cnt2[NE];

// ---------------- helpers ----------------
__device__ __forceinline__ uint32_t smem_u32(const void* p) {
    uint32_t a;
    asm("{ .reg .u64 t; cvta.to.shared.u64 t, %1; cvt.u32.u64 %0, t; }" : "=r"(a) : "l"(p));
    return a;
}
#define LDSM_X4(r0, r1, r2, r3, addr) \
    asm volatile("ldmatrix.sync.aligned.m8n8.x4.shared.b16 {%0,%1,%2,%3}, [%4];" \
        : "=r"(r0), "=r"(r1), "=r"(r2), "=r"(r3) : "r"(addr))
#define LDSM_X4T(r0, r1, r2, r3, addr) \
    asm volatile("ldmatrix.sync.aligned.m8n8.x4.trans.shared.b16 {%0,%1,%2,%3}, [%4];" \
        : "=r"(r0), "=r"(r1), "=r"(r2), "=r"(r3) : "r"(addr))
__device__ __forceinline__ void mma16816h(float* d, const uint32_t* a, const uint32_t* b) {
    asm volatile(
        "mma.sync.aligned.m16n8k16.row.col.f32.f16.f16.f32 "
        "{%0,%1,%2,%3}, {%4,%5,%6,%7}, {%8,%9}, {%0,%1,%2,%3};"
        : "+f"(d[0]), "+f"(d[1]), "+f"(d[2]), "+f"(d[3])
        : "r"(a[0]), "r"(a[1]), "r"(a[2]), "r"(a[3]), "r"(b[0]), "r"(b[1]));
}
__device__ __forceinline__ void cp16(uint32_t dst, const void* src) {
    asm volatile("cp.async.cg.shared.global [%0], [%1], 16;" :: "r"(dst), "l"(src));
}
#define CP_COMMIT() asm volatile("cp.async.commit_group;" ::: "memory")
#define CP_WAIT1()  asm volatile("cp.async.wait_group 1;" ::: "memory")

__device__ __forceinline__ uint32_t pack2h(float a, float b) {
    __half2 h = __floats2half2_rn(a, b);
    return *reinterpret_cast<uint32_t*>(&h);
}

// fp32 -> fp16, one segment: 8 elems/thread, streaming loads+stores
__global__ __launch_bounds__(256) void convert_seg_kernel(
    const float4* __restrict__ in, uint4* __restrict__ out) {
    size_t i = (size_t)blockIdx.x * 256 + threadIdx.x;
    float4 v0 = __ldcs(in + i * 2);
    float4 v1 = __ldcs(in + i * 2 + 1);
    uint4 h;
    h.x = pack2h(v0.x, v0.y);
    h.y = pack2h(v0.z, v0.w);
    h.z = pack2h(v1.x, v1.y);
    h.w = pack2h(v1.z, v1.w);
    __stcs(out + i, h);
}

// ---------------- GEMM tiling (fp16, BK=64, 3-stage, 2 CTAs/SM) ----------------
#define BM 128
#define BN 128
#define BK 64
#define A_PITCH_B 144         // bytes per A smem row (64*2 + 16 pad); verified conflict-free
#define B_PITCH_B 272         // bytes per B smem row (128*2 + 16 pad)
#define SA_BYTES (BM * A_PITCH_B)            // 18432
#define SB_BYTES (BK * B_PITCH_B)            // 17408
#define OFF_A 0
#define OFF_B SA_BYTES
#define STAGE_BYTES (SA_BYTES + SB_BYTES)    // 35840
#define NSTAGE 3
#define SM_TOTAL (NSTAGE * STAGE_BYTES)      // 107520 (x2 CTAs = 215KB <= 227KB)

// ---------------- fp16 warp-MMA GEMM core (cp.async 3-stage, BK=64) ----------------
template<int ACT, int OUT_F16>
__device__ __forceinline__ void gemm_core(
    const __half* __restrict__ A, const __half* __restrict__ Bw,
    const float* __restrict__ bias,
    float* __restrict__ Cf, __half* __restrict__ Ch,
    int Ncol, int K, int bm, int bn, float alpha)
{
    extern __shared__ char smem[];
    const int tid = threadIdx.x, w = tid >> 5, lane = tid & 31;
    const uint32_t sbase = smem_u32(smem);
    const int wm = (w >> 2) * 64, wn = (w & 3) * 32;

    // cp.async mapping: A: 2 threads/row, 4x16B each; B: 4 threads/row, 4x16B each
    const int ra = tid >> 1, ha = tid & 1;     // A row 0..127, half 0/1
    const int rb = tid >> 2, qb = tid & 3;     // B row 0..63, quarter 0..3
    const uint32_t a_dst0 = (uint32_t)ra * A_PITCH_B + (uint32_t)ha * 64;
    const uint32_t b_dst0 = (uint32_t)rb * B_PITCH_B + (uint32_t)qb * 64;
    const __half* aS = A + (size_t)(bm + ra) * K + ha * 32;
    const __half* bS = Bw + (size_t)rb * Ncol + bn + qb * 32;

    const uint32_t aoff = (uint32_t)(wm + (lane & 15)) * A_PITCH_B + ((lane >> 4) ? 16u : 0u);
    const uint32_t boff = (uint32_t)(lane & 15) * B_PITCH_B + (uint32_t)(wn + (lane >> 4) * 8) * 2;

    float acc[4][4][4];
    #pragma unroll
    for (int i = 0; i < 4; i++)
        #pragma unroll
        for (int j = 0; j < 4; j++)
            #pragma unroll
            for (int kq = 0; kq < 4; kq++) acc[i][j][kq] = 0.f;

    const int S = K / BK;

    // prologue: issue stages 0,1
    #pragma unroll
    for (int s = 0; s < NSTAGE - 1; s++) {
        const uint32_t stb = sbase + (uint32_t)s * STAGE_BYTES;
        const int k0 = s * BK;
        #pragma unroll
        for (int j = 0; j < 4; j++) {
            cp16(stb + OFF_A + a_dst0 + j * 16, aS + k0 + j * 8);
            cp16(stb + OFF_B + b_dst0 + j * 16, bS + (size_t)k0 * Ncol + j * 8);
        }
        CP_COMMIT();
    }

    int buf = 0, nbuf = NSTAGE - 1;
    for (int s = 0; s < S; s++) {
        CP_WAIT1();
        __syncthreads();
        if (s + NSTAGE - 1 < S) {
            const uint32_t stb = sbase + (uint32_t)nbuf * STAGE_BYTES;
            const int k0 = (s + NSTAGE - 1) * BK;
            #pragma unroll
            for (int j = 0; j < 4; j++) {
                cp16(stb + OFF_A + a_dst0 + j * 16, aS + k0 + j * 8);
                cp16(stb + OFF_B + b_dst0 + j * 16, bS + (size_t)k0 * Ncol + j * 8);
            }
        }
        CP_COMMIT();
        const uint32_t stb = sbase + (uint32_t)buf * STAGE_BYTES;
        #pragma unroll
        for (int ks = 0; ks < 4; ks++) {
            const int kb = ks * 16;
            uint32_t bh[2][4];
            #pragma unroll
            for (int np = 0; np < 2; np++) {
                uint32_t bd = stb + OFF_B + boff + (uint32_t)kb * B_PITCH_B + (uint32_t)np * 32;
                LDSM_X4T(bh[np][0], bh[np][1], bh[np][2], bh[np][3], bd);
            }
            #pragma unroll
            for (int mt = 0; mt < 4; mt++) {
                uint32_t ah[4];
                uint32_t ad = stb + OFF_A + aoff + (uint32_t)mt * (16 * A_PITCH_B) + (uint32_t)kb * 2;
                LDSM_X4(ah[0], ah[1], ah[2], ah[3], ad);
                #pragma unroll
                for (int nt = 0; nt < 4; nt++) {
                    uint32_t* pb = &bh[nt >> 1][(nt & 1) * 2];
                    mma16816h(acc[mt][nt], ah, pb);
                }
            }
        }
        buf = (buf == NSTAGE - 1) ? 0 : buf + 1;
        nbuf = (nbuf == NSTAGE - 1) ? 0 : nbuf + 1;
    }

    // --- epilogue ---
    const int lr = lane >> 2, lc = (lane & 3) * 2;
    #pragma unroll
    for (int mt = 0; mt < 4; mt++) {
        #pragma unroll
        for (int nt = 0; nt < 4; nt++) {
            int col = bn + wn + nt * 8 + lc;
            float b0 = bias[col], b1 = bias[col + 1];
            #pragma unroll
            for (int half = 0; half < 2; half++) {
                long long row = bm + wm + mt * 16 + lr + half * 8;
                float vx = acc[mt][nt][half * 2 + 0] + b0;
                float vy = acc[mt][nt][half * 2 + 1] + b1;
                if (ACT) {
                    vx = vx / (1.f + __expf(-vx));
                    vy = vy / (1.f + __expf(-vy));
                }
                vx *= alpha; vy *= alpha;
                if (OUT_F16) {
                    *(uint32_t*)(Ch + row * Ncol + col) = pack2h(vx, vy);
                } else {
                    *(float2*)(Cf + row * Ncol + col) = make_float2(vx, vy);
                }
            }
        }
    }
}

__device__ __forceinline__ int expert_used(int z) {
    return min(min(g_cnt1[z], CAP) + g_cnt2[z], CAP);
}

// merged GEMM stage 1: experts (z<8) and shared (z>=8), [*,1024]@[1024,4096] -> silu -> fp16
__global__ __launch_bounds__(256, 2) void gemm1_kernel(
    const float* __restrict__ b1, const float* __restrict__ sb1)
{
    const int z = blockIdx.z;
    const __half *A, *Bw;
    __half *Ch;
    const float* bias;
    int bm;
    if (z < NE) {
        bm = blockIdx.y * BM;
        if (bm >= expert_used(z)) return;
        A  = g_eif + (size_t)z * CAP * H_DIM;
        Bw = g_w1f + (size_t)z * H_DIM * F_DIM;
        bias = b1 + (size_t)z * F_DIM;
        Ch = g_hmf + (size_t)z * CAP * F_DIM;
    } else {
        int t = (z - NE) * gridDim.y + blockIdx.y;
        if (t >= N_TOK / BM) return;
        bm = t * BM;
        A  = g_xf;
        Bw = g_sw1f;
        bias = sb1;
        Ch = g_smf;
    }
    gemm_core<1, 1>(A, Bw, bias, nullptr, Ch, F_DIM, H_DIM, bm, blockIdx.x * BN, 1.f);
}

// merged GEMM stage 2: [*,4096]@[4096,1024] + bias -> fp32
__global__ __launch_bounds__(256, 2) void gemm2_kernel(
    const float* __restrict__ b2, const float* __restrict__ sb2, float* __restrict__ out)
{
    const int z = blockIdx.z;
    const __half *A, *Bw;
    float* Cf;
    const float* bias;
    int bm;
    float alpha;
    if (z < NE) {
        bm = blockIdx.y * BM;
        if (bm >= expert_used(z)) return;
        A  = g_hmf + (size_t)z * CAP * F_DIM;
        Bw = g_w2f + (size_t)z * F_DIM * H_DIM;
        bias = b2 + (size_t)z * H_DIM;
        Cf = g_expert_out + (size_t)z * CAP * H_DIM;
        alpha = 1.f;
    } else {
        int t = (z - NE) * gridDim.y + blockIdx.y;
        if (t >= N_TOK / BM) return;
        bm = t * BM;
        A  = g_smf;
        Bw = g_sw2f;
        bias = sb2;
        Cf = out;
        alpha = 0.1f;
    }
    gemm_core<0, 0>(A, Bw, bias, Cf, nullptr, H_DIM, F_DIM, bm, blockIdx.x * BN, alpha);
}

// ---------------- routing ----------------
__global__ void zero_counts_kernel() {
    int t = threadIdx.x;
    if (t < NE) { g_cnt1[t] = 0; g_cnt2[t] = 0; }
}

// router + top-1 slot assignment fused
__global__ void router_kernel(const float* __restrict__ x, const float* __restrict__ rw) {
    int n = blockIdx.x;
    int tid = threadIdx.x;
    float acc[NE];
    #pragma unroll
    for (int e = 0; e < NE; e++) acc[e] = 0.f;
    const float* xr = x + (size_t)n * H_DIM;
    for (int h = tid; h < H_DIM; h += 256) {
        float xv = xr[h];
        const float* r = rw + h * NE;
        #pragma unroll
        for (int e = 0; e < NE; e++) acc[e] += xv * r[e];
    }
    __shared__ float red[NE][256];
    #pragma unroll
    for (int e = 0; e < NE; e++) red[e][tid] = acc[e];
    __syncthreads();
    for (int s = 128; s > 0; s >>= 1) {
        if (tid < s) {
            #pragma unroll
            for (int e = 0; e < NE; e++) red[e][tid] += red[e][tid + s];
        }
        __syncthreads();
    }
    if (tid == 0) {
        float l[NE], m = -1e30f;
        #pragma unroll
        for (int e = 0; e < NE; e++) { l[e] = red[e][0]; m = fmaxf(m, l[e]); }
        float p[NE], s = 0.f;
        #pragma unroll
        for (int e = 0; e < NE; e++) { p[e] = expf(l[e] - m); s += p[e]; }
        #pragma unroll
        for (int e = 0; e < NE; e++) p[e] /= s;
        int i1 = 0;
        #pragma unroll
        for (int e = 1; e < NE; e++) if (p[e] > p[i1]) i1 = e;
        int i2 = -1; float best = -1.f;
        #pragma unroll
        for (int e = 0; e < NE; e++) if (e != i1 && p[e] > best) { best = p[e]; i2 = e; }
        g_e1[n] = i1; g_e2[n] = i2;
        g_g1[n] = p[i1]; g_g2[n] = p[i2];
        g_slot1[n] = atomicAdd(&g_cnt1[i1], 1);
    }
}

__global__ void assign2_kernel() {
    int n = blockIdx.x * 256 + threadIdx.x;
    if (n >= N_TOK) return;
    int e2 = g_e2[n];
    int off = min(g_cnt1[e2], CAP);
    int s2 = off + atomicAdd(&g_cnt2[e2], 1);
    g_slot2[n] = s2;
    float g1 = (g_slot1[n] < CAP) ? g_g1[n] : 0.f;
    float g2 = (s2 < CAP)         ? g_g2[n] : 0.f;
    float denom = fmaxf(g1 + g2, 1.1920929e-07f);
    g_g1[n] = g1 / denom;
    g_g2[n] = g2 / denom;
}

// scatter token into expert buffers (single fp16 plane)
__global__ void dispatch_kernel(const float* __restrict__ x) {
    int n = blockIdx.x;
    const float4* xr = (const float4*)(x + (size_t)n * H_DIM);
    int e1 = g_e1[n], s1 = g_slot1[n];
    int e2 = g_e2[n], s2 = g_slot2[n];
    uint2* d1 = (s1 < CAP) ? (uint2*)(g_eif + ((size_t)e1 * CAP + s1) * H_DIM) : nullptr;
    uint2* d2 = (s2 < CAP) ? (uint2*)(g_eif + ((size_t)e2 * CAP + s2) * H_DIM) : nullptr;
    for (int i = threadIdx.x; i < H_DIM / 4; i += 256) {
        float4 v = xr[i];
        uint2 hh = make_uint2(pack2h(v.x, v.y), pack2h(v.z, v.w));
        if (d1) d1[i] = hh;
        if (d2) d2[i] = hh;
    }
}

__global__ void combine_kernel(float* __restrict__ out) {
    int n = blockIdx.x;
    int e1 = g_e1[n], s1 = g_slot1[n];
    int e2 = g_e2[n], s2 = g_slot2[n];
    float g1 = g_g1[n], g2 = g_g2[n];
    const float4* p1 = (s1 < CAP) ? (const float4*)(g_expert_out + ((size_t)e1 * CAP + s1) * H_DIM) : nullptr;
    const float4* p2 = (s2 < CAP) ? (const float4*)(g_expert_out + ((size_t)e2 * CAP + s2) * H_DIM) : nullptr;
    float4* o = (float4*)(out + (size_t)n * H_DIM);
    for (int i = threadIdx.x; i < H_DIM / 4; i += 256) {
        float4 v = o[i];
        if (p1) { float4 a = p1[i]; v.x += g1 * a.x; v.y += g1 * a.y; v.z += g1 * a.z; v.w += g1 * a.w; }
        if (p2) { float4 a = p2[i]; v.x += g2 * a.x; v.y += g2 * a.y; v.z += g2 * a.z; v.w += g2 * a.w; }
        o[i] = v;
    }
}

// ---------------- launcher (fork-join streams kept from R13) ----------------
extern "C" void kernel_launch(void* const* d_in, const int* in_sizes, int n_in,
                              void* d_out, int out_size) {
    const float* x   = (const float*)d_in[0];
    const float* rw  = (const float*)d_in[1];
    const float* w1  = (const float*)d_in[2];
    const float* b1  = (const float*)d_in[3];
    const float* w2  = (const float*)d_in[4];
    const float* b2  = (const float*)d_in[5];
    const float* sw1 = (const float*)d_in[6];
    const float* sb1 = (const float*)d_in[7];
    const float* sw2 = (const float*)d_in[8];
    const float* sb2 = (const float*)d_in[9];
    float* out = (float*)d_out;

    __half *w1f, *w2f, *sw1f, *sw2f, *xf;
    cudaGetSymbolAddress((void**)&w1f,  g_w1f);
    cudaGetSymbolAddress((void**)&w2f,  g_w2f);
    cudaGetSymbolAddress((void**)&sw1f, g_sw1f);
    cudaGetSymbolAddress((void**)&sw2f, g_sw2f);
    cudaGetSymbolAddress((void**)&xf,   g_xf);

    static int inited = 0;
    static cudaStream_t s1, s2;
    static cudaEvent_t eFork, eMid, eJ1, eJ2;
    if (!inited) {
        cudaStreamCreateWithFlags(&s1, cudaStreamNonBlocking);
        cudaStreamCreateWithFlags(&s2, cudaStreamNonBlocking);
        cudaEventCreateWithFlags(&eFork, cudaEventDisableTiming);
        cudaEventCreateWithFlags(&eMid,  cudaEventDisableTiming);
        cudaEventCreateWithFlags(&eJ1,   cudaEventDisableTiming);
        cudaEventCreateWithFlags(&eJ2,   cudaEventDisableTiming);
        cudaFuncSetAttribute(gemm1_kernel, cudaFuncAttributeMaxDynamicSharedMemorySize, SM_TOTAL);
        cudaFuncSetAttribute(gemm2_kernel, cudaFuncAttributeMaxDynamicSharedMemorySize, SM_TOTAL);
        inited = 1;
    }

    // fork at t=0: s1 converts gemm1's weights (critical path) parallel to routing
    cudaEventRecord(eFork, 0);
    cudaStreamWaitEvent(s1, eFork, 0);
    convert_seg_kernel<<<(int)((size_t)NE * H_DIM * F_DIM / 2048), 256, 0, s1>>>((const float4*)w1,  (uint4*)w1f);
    convert_seg_kernel<<<(int)((size_t)H_DIM * F_DIM / 2048),      256, 0, s1>>>((const float4*)sw1, (uint4*)sw1f);
    cudaEventRecord(eJ1, s1);

    // main stream: routing chain + x convert + dispatch
    zero_counts_kernel<<<1, 32>>>();
    convert_seg_kernel<<<(int)((size_t)N_TOK * H_DIM / 2048), 256>>>((const float4*)x, (uint4*)xf);
    router_kernel<<<N_TOK, 256>>>(x, rw);
    assign2_kernel<<<N_TOK / 256, 256>>>();
    dispatch_kernel<<<N_TOK, 256>>>(x);

    // fork point for s2: AFTER dispatch, so its converts co-run with gemm1
    cudaEventRecord(eMid, 0);
    cudaStreamWaitEvent(s2, eMid, 0);
    convert_seg_kernel<<<(int)((size_t)NE * F_DIM * H_DIM / 2048), 256, 0, s2>>>((const float4*)w2,  (uint4*)w2f);
    convert_seg_kernel<<<(int)((size_t)F_DIM * H_DIM / 2048),      256, 0, s2>>>((const float4*)sw2, (uint4*)sw2f);
    cudaEventRecord(eJ2, s2);

    // gemm1 needs w1f/sw1f (s1) + dispatch output
    cudaStreamWaitEvent(0, eJ1, 0);
    {
        dim3 grid(F_DIM / BN, CAP / BM, NE + 4);
        gemm1_kernel<<<grid, 256, SM_TOTAL>>>(b1, sb1);
    }
    // gemm2 needs w2f/sw2f (s2, hidden under gemm1) + gemm1 output
    cudaStreamWaitEvent(0, eJ2, 0);
    {
        dim3 grid(H_DIM / BN, CAP / BM, NE + 4);
        gemm2_kernel<<<grid, 256, SM_TOTAL>>>(b2, sb2, out);
    }
    combine_kernel<<<N_TOK, 256>>>(out);
}

// round 15
// speedup vs baseline: 1.2686x; 1.2686x over previous
#include <cuda_runtime.h>
#include <cuda_fp16.h>
#include <math.h>
#include <stdint.h>

#define N_TOK 4096
#define H_DIM 1024
#define F_DIM 4096
#define NE 8
#define CAP 1280   // min(max(4, ceil(2*1.25*4096/8)), 4096)

// ---------------- scratch (device globals; no allocations allowed) ----------------
__device__ __half g_w1f [(size_t)NE * H_DIM * F_DIM];
__device__ __half g_w2f [(size_t)NE * F_DIM * H_DIM];
__device__ __half g_sw1f[(size_t)H_DIM * F_DIM];
__device__ __half g_sw2f[(size_t)F_DIM * H_DIM];
__device__ __half g_xf [(size_t)N_TOK * H_DIM];
__device__ __half g_eif[(size_t)NE * CAP * H_DIM];
__device__ __half g_hmf[(size_t)NE * CAP * F_DIM];
__device__ __half g_smf[(size_t)N_TOK * F_DIM];
__device__ float g_expert_out[(size_t)NE * CAP * H_DIM];
__device__ int   g_e1[N_TOK];
__device__ int   g_e2[N_TOK];
__device__ int   g_slot1[N_TOK];
__device__ int   g_slot2[N_TOK];
__device__ float g_g1[N_TOK];
__device__ float g_g2[N_TOK];
__device__ int   g_cnt1[NE];
__device__ int   g_cnt2[NE];

// ---------------- helpers ----------------
__device__ __forceinline__ uint32_t smem_u32(const void* p) {
    uint32_t a;
    asm("{ .reg .u64 t; cvta.to.shared.u64 t, %1; cvt.u32.u64 %0, t; }" : "=r"(a) : "l"(p));
    return a;
}
#define LDSM_X4(r0, r1, r2, r3, addr) \
    asm volatile("ldmatrix.sync.aligned.m8n8.x4.shared.b16 {%0,%1,%2,%3}, [%4];" \
        : "=r"(r0), "=r"(r1), "=r"(r2), "=r"(r3) : "r"(addr))
#define LDSM_X4T(r0, r1, r2, r3, addr) \
    asm volatile("ldmatrix.sync.aligned.m8n8.x4.trans.shared.b16 {%0,%1,%2,%3}, [%4];" \
        : "=r"(r0), "=r"(r1), "=r"(r2), "=r"(r3) : "r"(addr))
__device__ __forceinline__ void mma16816h(float* d, const uint32_t* a, const uint32_t* b) {
    asm volatile(
        "mma.sync.aligned.m16n8k16.row.col.f32.f16.f16.f32 "
        "{%0,%1,%2,%3}, {%4,%5,%6,%7}, {%8,%9}, {%0,%1,%2,%3};"
        : "+f"(d[0]), "+f"(d[1]), "+f"(d[2]), "+f"(d[3])
        : "r"(a[0]), "r"(a[1]), "r"(a[2]), "r"(a[3]), "r"(b[0]), "r"(b[1]));
}
__device__ __forceinline__ void cp16(uint32_t dst, const void* src) {
    asm volatile("cp.async.cg.shared.global [%0], [%1], 16;" :: "r"(dst), "l"(src));
}
#define CP_COMMIT() asm volatile("cp.async.commit_group;" ::: "memory")
#define CP_WAIT3()  asm volatile("cp.async.wait_group 3;" ::: "memory")

__device__ __forceinline__ uint32_t pack2h(float a, float b) {
    __half2 h = __floats2half2_rn(a, b);
    return *reinterpret_cast<uint32_t*>(&h);
}

// fp32 -> fp16, one segment: 8 elems/thread, streaming loads+stores
__global__ __launch_bounds__(256) void convert_seg_kernel(
    const float4* __restrict__ in, uint4* __restrict__ out) {
    size_t i = (size_t)blockIdx.x * 256 + threadIdx.x;
    float4 v0 = __ldcs(in + i * 2);
    float4 v1 = __ldcs(in + i * 2 + 1);
    uint4 h;
    h.x = pack2h(v0.x, v0.y);
    h.y = pack2h(v0.z, v0.w);
    h.z = pack2h(v1.x, v1.y);
    h.w = pack2h(v1.z, v1.w);
    __stcs(out + i, h);
}

// ---------------- GEMM tiling (R13-proven: fp16, BK=32, 5-stage, 2 CTAs/SM) ----------------
#define BM 128
#define BN 128
#define BK 32
#define A_PITCH_B 80          // bytes per A smem row (32*2 + 16 pad)
#define B_PITCH_B 272         // bytes per B smem row (128*2 + 16 pad)
#define SA_BYTES (BM * A_PITCH_B)            // 10240
#define SB_BYTES (BK * B_PITCH_B)            // 8704
#define OFF_A 0
#define OFF_B SA_BYTES
#define STAGE_BYTES (SA_BYTES + SB_BYTES)    // 18944
#define NSTAGE 5
#define SM_TOTAL (NSTAGE * STAGE_BYTES)      // 94720

// ---------------- fp16 warp-MMA GEMM core (cp.async 5-stage pipeline) ----------------
template<int ACT, int OUT_F16>
__device__ __forceinline__ void gemm_core(
    const __half* __restrict__ A, const __half* __restrict__ Bw,
    const float* __restrict__ bias,
    float* __restrict__ Cf, __half* __restrict__ Ch,
    int Ncol, int K, int bm, int bn, float alpha)
{
    extern __shared__ char smem[];
    const int tid = threadIdx.x, w = tid >> 5, lane = tid & 31;
    const uint32_t sbase = smem_u32(smem);
    const int wm = (w >> 2) * 64, wn = (w & 3) * 32;

    const int ra0 = tid >> 2, ca = (tid & 3);
    const int rb0 = tid >> 4, cb = (tid & 15);
    const uint32_t a_dst0 = (uint32_t)ra0 * A_PITCH_B + (uint32_t)ca * 16;
    const uint32_t b_dst0 = (uint32_t)rb0 * B_PITCH_B + (uint32_t)cb * 16;
    const __half* aS0 = A + (size_t)(bm + ra0) * K + ca * 8;
    const __half* aS1 = aS0 + (size_t)64 * K;
    const __half* bS0 = Bw + (size_t)rb0 * Ncol + bn + cb * 8;
    const __half* bS1 = bS0 + (size_t)16 * Ncol;

    const uint32_t aoff = (uint32_t)(wm + (lane & 15)) * A_PITCH_B + ((lane >> 4) ? 16u : 0u);
    const uint32_t boff = (uint32_t)(lane & 15) * B_PITCH_B + (uint32_t)(wn + (lane >> 4) * 8) * 2;

    float acc[4][4][4];
    #pragma unroll
    for (int i = 0; i < 4; i++)
        #pragma unroll
        for (int j = 0; j < 4; j++)
            #pragma unroll
            for (int kq = 0; kq < 4; kq++) acc[i][j][kq] = 0.f;

    const int S = K / BK;

    // prologue: issue stages 0..3
    #pragma unroll
    for (int s = 0; s < NSTAGE - 1; s++) {
        const uint32_t stb = sbase + (uint32_t)s * STAGE_BYTES;
        const int k0 = s * BK;
        cp16(stb + OFF_A + a_dst0,                  aS0 + k0);
        cp16(stb + OFF_A + a_dst0 + 64 * A_PITCH_B, aS1 + k0);
        cp16(stb + OFF_B + b_dst0,                  bS0 + (size_t)k0 * Ncol);
        cp16(stb + OFF_B + b_dst0 + 16 * B_PITCH_B, bS1 + (size_t)k0 * Ncol);
        CP_COMMIT();
    }

    int buf = 0, nbuf = NSTAGE - 1;
    for (int s = 0; s < S; s++) {
        CP_WAIT3();
        __syncthreads();
        if (s + NSTAGE - 1 < S) {
            const uint32_t stb = sbase + (uint32_t)nbuf * STAGE_BYTES;
            const int k0 = (s + NSTAGE - 1) * BK;
            cp16(stb + OFF_A + a_dst0,                  aS0 + k0);
            cp16(stb + OFF_A + a_dst0 + 64 * A_PITCH_B, aS1 + k0);
            cp16(stb + OFF_B + b_dst0,                  bS0 + (size_t)k0 * Ncol);
            cp16(stb + OFF_B + b_dst0 + 16 * B_PITCH_B, bS1 + (size_t)k0 * Ncol);
        }
        CP_COMMIT();
        const uint32_t stb = sbase + (uint32_t)buf * STAGE_BYTES;
        #pragma unroll
        for (int ks = 0; ks < 2; ks++) {
            const int kb = ks * 16;
            uint32_t bh[2][4];
            #pragma unroll
            for (int np = 0; np < 2; np++) {
                uint32_t bd = stb + OFF_B + boff + (uint32_t)kb * B_PITCH_B + (uint32_t)np * 32;
                LDSM_X4T(bh[np][0], bh[np][1], bh[np][2], bh[np][3], bd);
            }
            #pragma unroll
            for (int mt = 0; mt < 4; mt++) {
                uint32_t ah[4];
                uint32_t ad = stb + OFF_A + aoff + (uint32_t)mt * (16 * A_PITCH_B) + (uint32_t)kb * 2;
                LDSM_X4(ah[0], ah[1], ah[2], ah[3], ad);
                #pragma unroll
                for (int nt = 0; nt < 4; nt++) {
                    uint32_t* pb = &bh[nt >> 1][(nt & 1) * 2];
                    mma16816h(acc[mt][nt], ah, pb);
                }
            }
        }
        buf = (buf == NSTAGE - 1) ? 0 : buf + 1;
        nbuf = (nbuf == NSTAGE - 1) ? 0 : nbuf + 1;
    }

    // --- epilogue ---
    const int lr = lane >> 2, lc = (lane & 3) * 2;
    #pragma unroll
    for (int mt = 0; mt < 4; mt++) {
        #pragma unroll
        for (int nt = 0; nt < 4; nt++) {
            int col = bn + wn + nt * 8 + lc;
            float b0 = bias[col], b1 = bias[col + 1];
            #pragma unroll
            for (int half = 0; half < 2; half++) {
                long long row = bm + wm + mt * 16 + lr + half * 8;
                float vx = acc[mt][nt][half * 2 + 0] + b0;
                float vy = acc[mt][nt][half * 2 + 1] + b1;
                if (ACT) {
                    vx = vx / (1.f + __expf(-vx));
                    vy = vy / (1.f + __expf(-vy));
                }
                vx *= alpha; vy *= alpha;
                if (OUT_F16) {
                    *(uint32_t*)(Ch + row * Ncol + col) = pack2h(vx, vy);
                } else {
                    *(float2*)(Cf + row * Ncol + col) = make_float2(vx, vy);
                }
            }
        }
    }
}

__device__ __forceinline__ int expert_used(int z) {
    return min(min(g_cnt1[z], CAP) + g_cnt2[z], CAP);
}

// merged GEMM stage 1: experts (z<8) and shared (z>=8), [*,1024]@[1024,4096] -> silu -> fp16
__global__ __launch_bounds__(256, 2) void gemm1_kernel(
    const float* __restrict__ b1, const float* __restrict__ sb1)
{
    const int z = blockIdx.z;
    const __half *A, *Bw;
    __half *Ch;
    const float* bias;
    int bm;
    if (z < NE) {
        bm = blockIdx.y * BM;
        if (bm >= expert_used(z)) return;
        A  = g_eif + (size_t)z * CAP * H_DIM;
        Bw = g_w1f + (size_t)z * H_DIM * F_DIM;
        bias = b1 + (size_t)z * F_DIM;
        Ch = g_hmf + (size_t)z * CAP * F_DIM;
    } else {
        int t = (z - NE) * gridDim.y + blockIdx.y;
        if (t >= N_TOK / BM) return;
        bm = t * BM;
        A  = g_xf;
        Bw = g_sw1f;
        bias = sb1;
        Ch = g_smf;
    }
    gemm_core<1, 1>(A, Bw, bias, nullptr, Ch, F_DIM, H_DIM, bm, blockIdx.x * BN, 1.f);
}

// merged GEMM stage 2: [*,4096]@[4096,1024] + bias -> fp32
__global__ __launch_bounds__(256, 2) void gemm2_kernel(
    const float* __restrict__ b2, const float* __restrict__ sb2, float* __restrict__ out)
{
    const int z = blockIdx.z;
    const __half *A, *Bw;
    float* Cf;
    const float* bias;
    int bm;
    float alpha;
    if (z < NE) {
        bm = blockIdx.y * BM;
        if (bm >= expert_used(z)) return;
        A  = g_hmf + (size_t)z * CAP * F_DIM;
        Bw = g_w2f + (size_t)z * F_DIM * H_DIM;
        bias = b2 + (size_t)z * H_DIM;
        Cf = g_expert_out + (size_t)z * CAP * H_DIM;
        alpha = 1.f;
    } else {
        int t = (z - NE) * gridDim.y + blockIdx.y;
        if (t >= N_TOK / BM) return;
        bm = t * BM;
        A  = g_smf;
        Bw = g_sw2f;
        bias = sb2;
        Cf = out;
        alpha = 0.1f;
    }
    gemm_core<0, 0>(A, Bw, bias, Cf, nullptr, H_DIM, F_DIM, bm, blockIdx.x * BN, alpha);
}

// ---------------- routing ----------------
__global__ void zero_counts_kernel() {
    int t = threadIdx.x;
    if (t < NE) { g_cnt1[t] = 0; g_cnt2[t] = 0; }
}

// router + top-1 slot assignment fused
__global__ void router_kernel(const float* __restrict__ x, const float* __restrict__ rw) {
    int n = blockIdx.x;
    int tid = threadIdx.x;
    float acc[NE];
    #pragma unroll
    for (int e = 0; e < NE; e++) acc[e] = 0.f;
    const float* xr = x + (size_t)n * H_DIM;
    for (int h = tid; h < H_DIM; h += 256) {
        float xv = xr[h];
        const float* r = rw + h * NE;
        #pragma unroll
        for (int e = 0; e < NE; e++) acc[e] += xv * r[e];
    }
    __shared__ float red[NE][256];
    #pragma unroll
    for (int e = 0; e < NE; e++) red[e][tid] = acc[e];
    __syncthreads();
    for (int s = 128; s > 0; s >>= 1) {
        if (tid < s) {
            #pragma unroll
            for (int e = 0; e < NE; e++) red[e][tid] += red[e][tid + s];
        }
        __syncthreads();
    }
    if (tid == 0) {
        float l[NE], m = -1e30f;
        #pragma unroll
        for (int e = 0; e < NE; e++) { l[e] = red[e][0]; m = fmaxf(m, l[e]); }
        float p[NE], s = 0.f;
        #pragma unroll
        for (int e = 0; e < NE; e++) { p[e] = expf(l[e] - m); s += p[e]; }
        #pragma unroll
        for (int e = 0; e < NE; e++) p[e] /= s;
        int i1 = 0;
        #pragma unroll
        for (int e = 1; e < NE; e++) if (p[e] > p[i1]) i1 = e;
        int i2 = -1; float best = -1.f;
        #pragma unroll
        for (int e = 0; e < NE; e++) if (e != i1 && p[e] > best) { best = p[e]; i2 = e; }
        g_e1[n] = i1; g_e2[n] = i2;
        g_g1[n] = p[i1]; g_g2[n] = p[i2];
        g_slot1[n] = atomicAdd(&g_cnt1[i1], 1);
    }
}

__global__ void assign2_kernel() {
    int n = blockIdx.x * 256 + threadIdx.x;
    if (n >= N_TOK) return;
    int e2 = g_e2[n];
    int off = min(g_cnt1[e2], CAP);
    int s2 = off + atomicAdd(&g_cnt2[e2], 1);
    g_slot2[n] = s2;
    float g1 = (g_slot1[n] < CAP) ? g_g1[n] : 0.f;
    float g2 = (s2 < CAP)         ? g_g2[n] : 0.f;
    float denom = fmaxf(g1 + g2, 1.1920929e-07f);
    g_g1[n] = g1 / denom;
    g_g2[n] = g2 / denom;
}

// scatter token into expert buffers: copy already-converted fp16 rows from g_xf
__global__ void dispatch_kernel() {
    int n = blockIdx.x;
    const uint2* xr = (const uint2*)(g_xf + (size_t)n * H_DIM);
    int e1 = g_e1[n], s1 = g_slot1[n];
    int e2 = g_e2[n], s2 = g_slot2[n];
    uint2* d1 = (s1 < CAP) ? (uint2*)(g_eif + ((size_t)e1 * CAP + s1) * H_DIM) : nullptr;
    uint2* d2 = (s2 < CAP) ? (uint2*)(g_eif + ((size_t)e2 * CAP + s2) * H_DIM) : nullptr;
    for (int i = threadIdx.x; i < H_DIM / 4; i += 256) {
        uint2 hh = xr[i];
        if (d1) d1[i] = hh;
        if (d2) d2[i] = hh;
    }
}

__global__ void combine_kernel(float* __restrict__ out) {
    int n = blockIdx.x;
    int e1 = g_e1[n], s1 = g_slot1[n];
    int e2 = g_e2[n], s2 = g_slot2[n];
    float g1 = g_g1[n], g2 = g_g2[n];
    const float4* p1 = (s1 < CAP) ? (const float4*)(g_expert_out + ((size_t)e1 * CAP + s1) * H_DIM) : nullptr;
    const float4* p2 = (s2 < CAP) ? (const float4*)(g_expert_out + ((size_t)e2 * CAP + s2) * H_DIM) : nullptr;
    float4* o = (float4*)(out + (size_t)n * H_DIM);
    for (int i = threadIdx.x; i < H_DIM / 4; i += 256) {
        float4 v = o[i];
        if (p1) { float4 a = p1[i]; v.x += g1 * a.x; v.y += g1 * a.y; v.z += g1 * a.z; v.w += g1 * a.w; }
        if (p2) { float4 a = p2[i]; v.x += g2 * a.x; v.y += g2 * a.y; v.z += g2 * a.z; v.w += g2 * a.w; }
        o[i] = v;
    }
}

// ---------------- launcher (fork-join streams, R13-proven) ----------------
extern "C" void kernel_launch(void* const* d_in, const int* in_sizes, int n_in,
                              void* d_out, int out_size) {
    const float* x   = (const float*)d_in[0];
    const float* rw  = (const float*)d_in[1];
    const float* w1  = (const float*)d_in[2];
    const float* b1  = (const float*)d_in[3];
    const float* w2  = (const float*)d_in[4];
    const float* b2  = (const float*)d_in[5];
    const float* sw1 = (const float*)d_in[6];
    const float* sb1 = (const float*)d_in[7];
    const float* sw2 = (const float*)d_in[8];
    const float* sb2 = (const float*)d_in[9];
    float* out = (float*)d_out;

    __half *w1f, *w2f, *sw1f, *sw2f, *xf;
    cudaGetSymbolAddress((void**)&w1f,  g_w1f);
    cudaGetSymbolAddress((void**)&w2f,  g_w2f);
    cudaGetSymbolAddress((void**)&sw1f, g_sw1f);
    cudaGetSymbolAddress((void**)&sw2f, g_sw2f);
    cudaGetSymbolAddress((void**)&xf,   g_xf);

    static int inited = 0;
    static cudaStream_t s1, s2;
    static cudaEvent_t eFork, eMid, eJ1, eJ2;
    if (!inited) {
        cudaStreamCreateWithFlags(&s1, cudaStreamNonBlocking);
        cudaStreamCreateWithFlags(&s2, cudaStreamNonBlocking);
        cudaEventCreateWithFlags(&eFork, cudaEventDisableTiming);
        cudaEventCreateWithFlags(&eMid,  cudaEventDisableTiming);
        cudaEventCreateWithFlags(&eJ1,   cudaEventDisableTiming);
        cudaEventCreateWithFlags(&eJ2,   cudaEventDisableTiming);
        cudaFuncSetAttribute(gemm1_kernel, cudaFuncAttributeMaxDynamicSharedMemorySize, SM_TOTAL);
        cudaFuncSetAttribute(gemm2_kernel, cudaFuncAttributeMaxDynamicSharedMemorySize, SM_TOTAL);
        inited = 1;
    }

    // fork at t=0: s1 converts gemm1's weights (critical path) parallel to routing
    cudaEventRecord(eFork, 0);
    cudaStreamWaitEvent(s1, eFork, 0);
    convert_seg_kernel<<<(int)((size_t)NE * H_DIM * F_DIM / 2048), 256, 0, s1>>>((const float4*)w1,  (uint4*)w1f);
    convert_seg_kernel<<<(int)((size_t)H_DIM * F_DIM / 2048),      256, 0, s1>>>((const float4*)sw1, (uint4*)sw1f);
    cudaEventRecord(eJ1, s1);

    // main stream: routing chain + x convert + dispatch (dispatch reads g_xf)
    zero_counts_kernel<<<1, 32>>>();
    convert_seg_kernel<<<(int)((size_t)N_TOK * H_DIM / 2048), 256>>>((const float4*)x, (uint4*)xf);
    router_kernel<<<N_TOK, 256>>>(x, rw);
    assign2_kernel<<<N_TOK / 256, 256>>>();
    dispatch_kernel<<<N_TOK, 256>>>();

    // fork point for s2: AFTER dispatch, so its converts co-run with gemm1
    cudaEventRecord(eMid, 0);
    cudaStreamWaitEvent(s2, eMid, 0);
    convert_seg_kernel<<<(int)((size_t)NE * F_DIM * H_DIM / 2048), 256, 0, s2>>>((const float4*)w2,  (uint4*)w2f);
    convert_seg_kernel<<<(int)((size_t)F_DIM * H_DIM / 2048),      256, 0, s2>>>((const float4*)sw2, (uint4*)sw2f);
    cudaEventRecord(eJ2, s2);

    // gemm1 needs w1f/sw1f (s1) + dispatch output
    cudaStreamWaitEvent(0, eJ1, 0);
    {
        dim3 grid(F_DIM / BN, CAP / BM, NE + 4);
        gemm1_kernel<<<grid, 256, SM_TOTAL>>>(b1, sb1);
    }
    // gemm2 needs w2f/sw2f (s2, hidden under gemm1) + gemm1 output
    cudaStreamWaitEvent(0, eJ2, 0);
    {
        dim3 grid(H_DIM / BN, CAP / BM, NE + 4);
        gemm2_kernel<<<grid, 256, SM_TOTAL>>>(b2, sb2, out);
    }
    combine_kernel<<<N_TOK, 256>>>(out);
}

// round 16
// speedup vs baseline: 1.3249x; 1.0444x over previous
#include <cuda_runtime.h>
#include <cuda_fp16.h>
#include <math.h>
#include <stdint.h>

#define N_TOK 4096
#define H_DIM 1024
#define F_DIM 4096
#define NE 8
#define CAP 1280   // min(max(4, ceil(2*1.25*4096/8)), 4096)

// ---------------- scratch (device globals; no allocations allowed) ----------------
__device__ __half g_w1f [(size_t)NE * H_DIM * F_DIM];
__device__ __half g_w2f [(size_t)NE * F_DIM * H_DIM];
__device__ __half g_sw1f[(size_t)H_DIM * F_DIM];
__device__ __half g_sw2f[(size_t)F_DIM * H_DIM];
__device__ __half g_xf [(size_t)N_TOK * H_DIM];
__device__ __half g_eif[(size_t)NE * CAP * H_DIM];
__device__ __half g_hmf[(size_t)NE * CAP * F_DIM];
__device__ __half g_smf[(size_t)N_TOK * F_DIM];
__device__ float g_expert_out[(size_t)NE * CAP * H_DIM];
__device__ int   g_e1[N_TOK];
__device__ int   g_e2[N_TOK];
__device__ int   g_slot1[N_TOK];
__device__ int   g_slot2[N_TOK];
__device__ float g_g1[N_TOK];
__device__ float g_g2[N_TOK];
__device__ int   g_cnt1[NE];
__device__ int   g_cnt2[NE];

// ---------------- helpers ----------------
__device__ __forceinline__ uint32_t smem_u32(const void* p) {
    uint32_t a;
    asm("{ .reg .u64 t; cvta.to.shared.u64 t, %1; cvt.u32.u64 %0, t; }" : "=r"(a) : "l"(p));
    return a;
}
#define LDSM_X4(r0, r1, r2, r3, addr) \
    asm volatile("ldmatrix.sync.aligned.m8n8.x4.shared.b16 {%0,%1,%2,%3}, [%4];" \
        : "=r"(r0), "=r"(r1), "=r"(r2), "=r"(r3) : "r"(addr))
#define LDSM_X4T(r0, r1, r2, r3, addr) \
    asm volatile("ldmatrix.sync.aligned.m8n8.x4.trans.shared.b16 {%0,%1,%2,%3}, [%4];" \
        : "=r"(r0), "=r"(r1), "=r"(r2), "=r"(r3) : "r"(addr))
__device__ __forceinline__ void mma16816h(float* d, const uint32_t* a, const uint32_t* b) {
    asm volatile(
        "mma.sync.aligned.m16n8k16.row.col.f32.f16.f16.f32 "
        "{%0,%1,%2,%3}, {%4,%5,%6,%7}, {%8,%9}, {%0,%1,%2,%3};"
        : "+f"(d[0]), "+f"(d[1]), "+f"(d[2]), "+f"(d[3])
        : "r"(a[0]), "r"(a[1]), "r"(a[2]), "r"(a[3]), "r"(b[0]), "r"(b[1]));
}
__device__ __forceinline__ void cp16(uint32_t dst, const void* src) {
    asm volatile("cp.async.cg.shared.global [%0], [%1], 16;" :: "r"(dst), "l"(src));
}
#define CP_COMMIT() asm volatile("cp.async.commit_group;" ::: "memory")
#define CP_WAIT3()  asm volatile("cp.async.wait_group 3;" ::: "memory")

__device__ __forceinline__ uint32_t pack2h(float a, float b) {
    __half2 h = __floats2half2_rn(a, b);
    return *reinterpret_cast<uint32_t*>(&h);
}

// fp32 -> fp16, one segment: 8 elems/thread, streaming loads+stores
__global__ __launch_bounds__(256) void convert_seg_kernel(
    const float4* __restrict__ in, uint4* __restrict__ out) {
    size_t i = (size_t)blockIdx.x * 256 + threadIdx.x;
    float4 v0 = __ldcs(in + i * 2);
    float4 v1 = __ldcs(in + i * 2 + 1);
    uint4 h;
    h.x = pack2h(v0.x, v0.y);
    h.y = pack2h(v0.z, v0.w);
    h.z = pack2h(v1.x, v1.y);
    h.w = pack2h(v1.z, v1.w);
    __stcs(out + i, h);
}

// x convert + zero the routing counters (block 0)
__global__ __launch_bounds__(256) void convert_x_kernel(
    const float4* __restrict__ in, uint4* __restrict__ out) {
    if (blockIdx.x == 0 && threadIdx.x < NE) {
        g_cnt1[threadIdx.x] = 0;
        g_cnt2[threadIdx.x] = 0;
    }
    size_t i = (size_t)blockIdx.x * 256 + threadIdx.x;
    float4 v0 = __ldcs(in + i * 2);
    float4 v1 = __ldcs(in + i * 2 + 1);
    uint4 h;
    h.x = pack2h(v0.x, v0.y);
    h.y = pack2h(v0.z, v0.w);
    h.z = pack2h(v1.x, v1.y);
    h.w = pack2h(v1.z, v1.w);
    __stcs(out + i, h);
}

// ---------------- GEMM tiling (proven: fp16, BK=32, 5-stage, 2 CTAs/SM) ----------------
#define BM 128
#define BN 128
#define BK 32
#define A_PITCH_B 80
#define B_PITCH_B 272
#define SA_BYTES (BM * A_PITCH_B)            // 10240
#define SB_BYTES (BK * B_PITCH_B)            // 8704
#define OFF_A 0
#define OFF_B SA_BYTES
#define STAGE_BYTES (SA_BYTES + SB_BYTES)    // 18944
#define NSTAGE 5
#define SM_TOTAL (NSTAGE * STAGE_BYTES)      // 94720

template<int ACT, int OUT_F16>
__device__ __forceinline__ void gemm_core(
    const __half* __restrict__ A, const __half* __restrict__ Bw,
    const float* __restrict__ bias,
    float* __restrict__ Cf, __half* __restrict__ Ch,
    int Ncol, int K, int bm, int bn, float alpha)
{
    extern __shared__ char smem[];
    const int tid = threadIdx.x, w = tid >> 5, lane = tid & 31;
    const uint32_t sbase = smem_u32(smem);
    const int wm = (w >> 2) * 64, wn = (w & 3) * 32;

    const int ra0 = tid >> 2, ca = (tid & 3);
    const int rb0 = tid >> 4, cb = (tid & 15);
    const uint32_t a_dst0 = (uint32_t)ra0 * A_PITCH_B + (uint32_t)ca * 16;
    const uint32_t b_dst0 = (uint32_t)rb0 * B_PITCH_B + (uint32_t)cb * 16;
    const __half* aS0 = A + (size_t)(bm + ra0) * K + ca * 8;
    const __half* aS1 = aS0 + (size_t)64 * K;
    const __half* bS0 = Bw + (size_t)rb0 * Ncol + bn + cb * 8;
    const __half* bS1 = bS0 + (size_t)16 * Ncol;

    const uint32_t aoff = (uint32_t)(wm + (lane & 15)) * A_PITCH_B + ((lane >> 4) ? 16u : 0u);
    const uint32_t boff = (uint32_t)(lane & 15) * B_PITCH_B + (uint32_t)(wn + (lane >> 4) * 8) * 2;

    float acc[4][4][4];
    #pragma unroll
    for (int i = 0; i < 4; i++)
        #pragma unroll
        for (int j = 0; j < 4; j++)
            #pragma unroll
            for (int kq = 0; kq < 4; kq++) acc[i][j][kq] = 0.f;

    const int S = K / BK;

    #pragma unroll
    for (int s = 0; s < NSTAGE - 1; s++) {
        const uint32_t stb = sbase + (uint32_t)s * STAGE_BYTES;
        const int k0 = s * BK;
        cp16(stb + OFF_A + a_dst0,                  aS0 + k0);
        cp16(stb + OFF_A + a_dst0 + 64 * A_PITCH_B, aS1 + k0);
        cp16(stb + OFF_B + b_dst0,                  bS0 + (size_t)k0 * Ncol);
        cp16(stb + OFF_B + b_dst0 + 16 * B_PITCH_B, bS1 + (size_t)k0 * Ncol);
        CP_COMMIT();
    }

    int buf = 0, nbuf = NSTAGE - 1;
    for (int s = 0; s < S; s++) {
        CP_WAIT3();
        __syncthreads();
        if (s + NSTAGE - 1 < S) {
            const uint32_t stb = sbase + (uint32_t)nbuf * STAGE_BYTES;
            const int k0 = (s + NSTAGE - 1) * BK;
            cp16(stb + OFF_A + a_dst0,                  aS0 + k0);
            cp16(stb + OFF_A + a_dst0 + 64 * A_PITCH_B, aS1 + k0);
            cp16(stb + OFF_B + b_dst0,                  bS0 + (size_t)k0 * Ncol);
            cp16(stb + OFF_B + b_dst0 + 16 * B_PITCH_B, bS1 + (size_t)k0 * Ncol);
        }
        CP_COMMIT();
        const uint32_t stb = sbase + (uint32_t)buf * STAGE_BYTES;
        #pragma unroll
        for (int ks = 0; ks < 2; ks++) {
            const int kb = ks * 16;
            uint32_t bh[2][4];
            #pragma unroll
            for (int np = 0; np < 2; np++) {
                uint32_t bd = stb + OFF_B + boff + (uint32_t)kb * B_PITCH_B + (uint32_t)np * 32;
                LDSM_X4T(bh[np][0], bh[np][1], bh[np][2], bh[np][3], bd);
            }
            #pragma unroll
            for (int mt = 0; mt < 4; mt++) {
                uint32_t ah[4];
                uint32_t ad = stb + OFF_A + aoff + (uint32_t)mt * (16 * A_PITCH_B) + (uint32_t)kb * 2;
                LDSM_X4(ah[0], ah[1], ah[2], ah[3], ad);
                #pragma unroll
                for (int nt = 0; nt < 4; nt++) {
                    uint32_t* pb = &bh[nt >> 1][(nt & 1) * 2];
                    mma16816h(acc[mt][nt], ah, pb);
                }
            }
        }
        buf = (buf == NSTAGE - 1) ? 0 : buf + 1;
        nbuf = (nbuf == NSTAGE - 1) ? 0 : nbuf + 1;
    }

    // --- epilogue ---
    const int lr = lane >> 2, lc = (lane & 3) * 2;
    #pragma unroll
    for (int mt = 0; mt < 4; mt++) {
        #pragma unroll
        for (int nt = 0; nt < 4; nt++) {
            int col = bn + wn + nt * 8 + lc;
            float b0 = bias[col], b1 = bias[col + 1];
            #pragma unroll
            for (int half = 0; half < 2; half++) {
                long long row = bm + wm + mt * 16 + lr + half * 8;
                float vx = acc[mt][nt][half * 2 + 0] + b0;
                float vy = acc[mt][nt][half * 2 + 1] + b1;
                if (ACT) {
                    vx = vx / (1.f + __expf(-vx));
                    vy = vy / (1.f + __expf(-vy));
                }
                vx *= alpha; vy *= alpha;
                if (OUT_F16) {
                    *(uint32_t*)(Ch + row * Ncol + col) = pack2h(vx, vy);
                } else {
                    *(float2*)(Cf + row * Ncol + col) = make_float2(vx, vy);
                }
            }
        }
    }
}

__device__ __forceinline__ int expert_used(int z) {
    return min(min(g_cnt1[z], CAP) + g_cnt2[z], CAP);
}

// ---- split GEMM wrappers: expert chain vs shared chain ----
__global__ __launch_bounds__(256, 2) void gemm1_exp_kernel(const float* __restrict__ b1) {
    const int z = blockIdx.z;
    const int bm = blockIdx.y * BM;
    if (bm >= expert_used(z)) return;
    gemm_core<1, 1>(g_eif + (size_t)z * CAP * H_DIM, g_w1f + (size_t)z * H_DIM * F_DIM,
                    b1 + (size_t)z * F_DIM, nullptr, g_hmf + (size_t)z * CAP * F_DIM,
                    F_DIM, H_DIM, bm, blockIdx.x * BN, 1.f);
}
__global__ __launch_bounds__(256, 2) void gemm1_sh_kernel(const float* __restrict__ sb1) {
    gemm_core<1, 1>(g_xf, g_sw1f, sb1, nullptr, g_smf,
                    F_DIM, H_DIM, blockIdx.y * BM, blockIdx.x * BN, 1.f);
}
__global__ __launch_bounds__(256, 2) void gemm2_exp_kernel(const float* __restrict__ b2) {
    const int z = blockIdx.z;
    const int bm = blockIdx.y * BM;
    if (bm >= expert_used(z)) return;
    gemm_core<0, 0>(g_hmf + (size_t)z * CAP * F_DIM, g_w2f + (size_t)z * F_DIM * H_DIM,
                    b2 + (size_t)z * H_DIM, g_expert_out + (size_t)z * CAP * H_DIM, nullptr,
                    H_DIM, F_DIM, bm, blockIdx.x * BN, 1.f);
}
__global__ __launch_bounds__(256, 2) void gemm2_sh_kernel(const float* __restrict__ sb2,
                                                          float* __restrict__ out) {
    gemm_core<0, 0>(g_smf, g_sw2f, sb2, out, nullptr,
                    H_DIM, F_DIM, blockIdx.y * BM, blockIdx.x * BN, 0.1f);
}

// ---------------- routing ----------------
// router + top-1 slot assignment fused
__global__ void router_kernel(const float* __restrict__ x, const float* __restrict__ rw) {
    int n = blockIdx.x;
    int tid = threadIdx.x;
    float acc[NE];
    #pragma unroll
    for (int e = 0; e < NE; e++) acc[e] = 0.f;
    const float* xr = x + (size_t)n * H_DIM;
    for (int h = tid; h < H_DIM; h += 256) {
        float xv = xr[h];
        const float* r = rw + h * NE;
        #pragma unroll
        for (int e = 0; e < NE; e++) acc[e] += xv * r[e];
    }
    __shared__ float red[NE][256];
    #pragma unroll
    for (int e = 0; e < NE; e++) red[e][tid] = acc[e];
    __syncthreads();
    for (int s = 128; s > 0; s >>= 1) {
        if (tid < s) {
            #pragma unroll
            for (int e = 0; e < NE; e++) red[e][tid] += red[e][tid + s];
        }
        __syncthreads();
    }
    if (tid == 0) {
        float l[NE], m = -1e30f;
        #pragma unroll
        for (int e = 0; e < NE; e++) { l[e] = red[e][0]; m = fmaxf(m, l[e]); }
        float p[NE], s = 0.f;
        #pragma unroll
        for (int e = 0; e < NE; e++) { p[e] = expf(l[e] - m); s += p[e]; }
        #pragma unroll
        for (int e = 0; e < NE; e++) p[e] /= s;
        int i1 = 0;
        #pragma unroll
        for (int e = 1; e < NE; e++) if (p[e] > p[i1]) i1 = e;
        int i2 = -1; float best = -1.f;
        #pragma unroll
        for (int e = 0; e < NE; e++) if (e != i1 && p[e] > best) { best = p[e]; i2 = e; }
        g_e1[n] = i1; g_e2[n] = i2;
        g_g1[n] = p[i1]; g_g2[n] = p[i2];
        g_slot1[n] = atomicAdd(&g_cnt1[i1], 1);
    }
}

// dispatch with fused top-2 slot assignment + gate finalization
__global__ void dispatch_kernel() {
    int n = blockIdx.x;
    int tid = threadIdx.x;
    __shared__ int sh_e1, sh_e2, sh_s1, sh_s2;
    if (tid == 0) {
        int e2 = g_e2[n];
        int off = min(g_cnt1[e2], CAP);       // cnt1 final (router completed)
        int s2 = off + atomicAdd(&g_cnt2[e2], 1);
        g_slot2[n] = s2;
        float g1 = (g_slot1[n] < CAP) ? g_g1[n] : 0.f;
        float g2 = (s2 < CAP)         ? g_g2[n] : 0.f;
        float denom = fmaxf(g1 + g2, 1.1920929e-07f);
        g_g1[n] = g1 / denom;
        g_g2[n] = g2 / denom;
        sh_e1 = g_e1[n]; sh_e2 = e2;
        sh_s1 = g_slot1[n]; sh_s2 = s2;
    }
    __syncthreads();
    const uint2* xr = (const uint2*)(g_xf + (size_t)n * H_DIM);
    uint2* d1 = (sh_s1 < CAP) ? (uint2*)(g_eif + ((size_t)sh_e1 * CAP + sh_s1) * H_DIM) : nullptr;
    uint2* d2 = (sh_s2 < CAP) ? (uint2*)(g_eif + ((size_t)sh_e2 * CAP + sh_s2) * H_DIM) : nullptr;
    for (int i = tid; i < H_DIM / 4; i += 256) {
        uint2 hh = xr[i];
        if (d1) d1[i] = hh;
        if (d2) d2[i] = hh;
    }
}

__global__ void combine_kernel(float* __restrict__ out) {
    int n = blockIdx.x;
    int e1 = g_e1[n], s1 = g_slot1[n];
    int e2 = g_e2[n], s2 = g_slot2[n];
    float g1 = g_g1[n], g2 = g_g2[n];
    const float4* p1 = (s1 < CAP) ? (const float4*)(g_expert_out + ((size_t)e1 * CAP + s1) * H_DIM) : nullptr;
    const float4* p2 = (s2 < CAP) ? (const float4*)(g_expert_out + ((size_t)e2 * CAP + s2) * H_DIM) : nullptr;
    float4* o = (float4*)(out + (size_t)n * H_DIM);
    for (int i = threadIdx.x; i < H_DIM / 4; i += 256) {
        float4 v = o[i];
        if (p1) { float4 a = p1[i]; v.x += g1 * a.x; v.y += g1 * a.y; v.z += g1 * a.z; v.w += g1 * a.w; }
        if (p2) { float4 a = p2[i]; v.x += g2 * a.x; v.y += g2 * a.y; v.z += g2 * a.z; v.w += g2 * a.w; }
        o[i] = v;
    }
}

// ---------------- launcher: two overlapped dependency chains ----------------
extern "C" void kernel_launch(void* const* d_in, const int* in_sizes, int n_in,
                              void* d_out, int out_size) {
    const float* x   = (const float*)d_in[0];
    const float* rw  = (const float*)d_in[1];
    const float* w1  = (const float*)d_in[2];
    const float* b1  = (const float*)d_in[3];
    const float* w2  = (const float*)d_in[4];
    const float* b2  = (const float*)d_in[5];
    const float* sw1 = (const float*)d_in[6];
    const float* sb1 = (const float*)d_in[7];
    const float* sw2 = (const float*)d_in[8];
    const float* sb2 = (const float*)d_in[9];
    float* out = (float*)d_out;

    __half *w1f, *w2f, *sw1f, *sw2f, *xf;
    cudaGetSymbolAddress((void**)&w1f,  g_w1f);
    cudaGetSymbolAddress((void**)&w2f,  g_w2f);
    cudaGetSymbolAddress((void**)&sw1f, g_sw1f);
    cudaGetSymbolAddress((void**)&sw2f, g_sw2f);
    cudaGetSymbolAddress((void**)&xf,   g_xf);

    static int inited = 0;
    static cudaStream_t s1, s2, s3;
    static cudaEvent_t eFork, eX, eSW1, eW1, eMid, eJ2, eB;
    if (!inited) {
        cudaStreamCreateWithFlags(&s1, cudaStreamNonBlocking);
        cudaStreamCreateWithFlags(&s2, cudaStreamNonBlocking);
        cudaStreamCreateWithFlags(&s3, cudaStreamNonBlocking);
        cudaEventCreateWithFlags(&eFork, cudaEventDisableTiming);
        cudaEventCreateWithFlags(&eX,    cudaEventDisableTiming);
        cudaEventCreateWithFlags(&eSW1,  cudaEventDisableTiming);
        cudaEventCreateWithFlags(&eW1,   cudaEventDisableTiming);
        cudaEventCreateWithFlags(&eMid,  cudaEventDisableTiming);
        cudaEventCreateWithFlags(&eJ2,   cudaEventDisableTiming);
        cudaEventCreateWithFlags(&eB,    cudaEventDisableTiming);
        cudaFuncSetAttribute(gemm1_exp_kernel, cudaFuncAttributeMaxDynamicSharedMemorySize, SM_TOTAL);
        cudaFuncSetAttribute(gemm1_sh_kernel,  cudaFuncAttributeMaxDynamicSharedMemorySize, SM_TOTAL);
        cudaFuncSetAttribute(gemm2_exp_kernel, cudaFuncAttributeMaxDynamicSharedMemorySize, SM_TOTAL);
        cudaFuncSetAttribute(gemm2_sh_kernel,  cudaFuncAttributeMaxDynamicSharedMemorySize, SM_TOTAL);
        inited = 1;
    }

    // --- fork s1 at t=0: sw1 first (small; unblocks shared chain), then w1 ---
    cudaEventRecord(eFork, 0);
    cudaStreamWaitEvent(s1, eFork, 0);
    convert_seg_kernel<<<(int)((size_t)H_DIM * F_DIM / 2048),      256, 0, s1>>>((const float4*)sw1, (uint4*)sw1f);
    cudaEventRecord(eSW1, s1);
    convert_seg_kernel<<<(int)((size_t)NE * H_DIM * F_DIM / 2048), 256, 0, s1>>>((const float4*)w1,  (uint4*)w1f);
    cudaEventRecord(eW1, s1);

    // --- main: x convert (+counter zero) -> routing -> dispatch ---
    convert_x_kernel<<<(int)((size_t)N_TOK * H_DIM / 2048), 256>>>((const float4*)x, (uint4*)xf);
    cudaEventRecord(eX, 0);
    router_kernel<<<N_TOK, 256>>>(x, rw);
    dispatch_kernel<<<N_TOK, 256>>>();
    cudaEventRecord(eMid, 0);

    // --- s2: stage-2 weight converts, co-running with the GEMMs ---
    cudaStreamWaitEvent(s2, eMid, 0);
    convert_seg_kernel<<<(int)((size_t)NE * F_DIM * H_DIM / 2048), 256, 0, s2>>>((const float4*)w2,  (uint4*)w2f);
    convert_seg_kernel<<<(int)((size_t)F_DIM * H_DIM / 2048),      256, 0, s2>>>((const float4*)sw2, (uint4*)sw2f);
    cudaEventRecord(eJ2, s2);

    // --- chain B (s3): shared expert, independent of routing ---
    cudaStreamWaitEvent(s3, eX, 0);
    cudaStreamWaitEvent(s3, eSW1, 0);
    {
        dim3 grid(F_DIM / BN, N_TOK / BM, 1);
        gemm1_sh_kernel<<<grid, 256, SM_TOTAL, s3>>>(sb1);
    }
    cudaStreamWaitEvent(s3, eJ2, 0);
    {
        dim3 grid(H_DIM / BN, N_TOK / BM, 1);
        gemm2_sh_kernel<<<grid, 256, SM_TOTAL, s3>>>(sb2, out);
    }
    cudaEventRecord(eB, s3);

    // --- chain A (main): expert GEMMs ---
    cudaStreamWaitEvent(0, eW1, 0);
    {
        dim3 grid(F_DIM / BN, CAP / BM, NE);
        gemm1_exp_kernel<<<grid, 256, SM_TOTAL>>>(b1);
    }
    cudaStreamWaitEvent(0, eJ2, 0);
    {
        dim3 grid(H_DIM / BN, CAP / BM, NE);
        gemm2_exp_kernel<<<grid, 256, SM_TOTAL>>>(b2);
    }
    // join chain B, then combine expert outputs into out (which holds 0.1*shared)
    cudaStreamWaitEvent(0, eB, 0);
    combine_kernel<<<N_TOK, 256>>>(out);
}